// round 17
// baseline (speedup 1.0000x reference)
#include <cuda_runtime.h>

// MissingValueImputer — algebraically reduced (R2): GAT output is exactly
// relu(h0 @ gat_W^T), independent of node index and adjacency.
// R14: phase 2 & adjacency made COALESCED. R13's per-thread-owns-row gatW
// reads cost 32 L1 wavefronts per LDG (16K wf/SM = ~9us, the measured
// L1=55%). Now: warp = 32 rows as 4 c-subgroups x 8 f-lanes, 128B-chunk
// coalesced loads, h0 in registers, 3-round shfl reductions.

#define BW 512
#define NN 128
#define FF 128
#define CC 512
#define TPB 512
#define GRID 128

// smem (floats):
//   pool [0,8192): ph1 xs4[512] + red1[4096]@512 ; adj @4608 ; ph3 red3[8192]
//   h0s4 [8192,8704):  h0s4[f*4+r]
//   ps4  [8704,10752): ps4[c*4+r]
#define SM_H0S 8192
#define SM_PS  8704
#define SM_TOT 10752

__global__ __launch_bounds__(TPB, 1)
void fused_kernel(const float* __restrict__ x, const float* __restrict__ mask,
                  const float* __restrict__ emb, const float* __restrict__ gatW,
                  const float* __restrict__ fpW, const float* __restrict__ fpb,
                  const float* __restrict__ opW, const float* __restrict__ opb,
                  const int* __restrict__ kptr,
                  float* __restrict__ out, float* __restrict__ adj_out) {
    __shared__ __align__(16) float sm[SM_TOT];
    const int t = threadIdx.x;
    const int blk = blockIdx.x;
    const int b0 = blk * 4;
    float* h0s4 = sm + SM_H0S;
    float* ps4  = sm + SM_PS;

    // ============ Phase 1: h0 (t<256) + adjacency (256<=t<384) =============
    if (t < 256) {
        // h0[r][o] = fp_b[o] + sum_f x[r][f] * fpW[f][o], partials by f-group
        float* xs4  = sm;        // [128 f][4 r]
        float* red1 = sm + 512;  // [8 fq][4 r][32 o4][4]
        for (int i = t; i < 512; i += 256) {
            const int f = i & 127, r = i >> 7;
            xs4[f * 4 + r] = x[b0 * NN + i];
        }
        asm volatile("bar.sync 3, 256;" ::: "memory");

        const int o4 = t & 31, fq = t >> 5;
        const float4* fw4 = (const float4*)fpW;  // [f][o4]
        float4 a0 = {0,0,0,0}, a1 = {0,0,0,0}, a2 = {0,0,0,0}, a3 = {0,0,0,0};
        #pragma unroll 8
        for (int f = fq * 16; f < fq * 16 + 16; ++f) {
            const float4 wv = fw4[f * 32 + o4];              // coalesced LDG.128
            const float4 xv = *(const float4*)&xs4[f * 4];   // bcast LDS.128
            a0.x += xv.x * wv.x; a0.y += xv.x * wv.y; a0.z += xv.x * wv.z; a0.w += xv.x * wv.w;
            a1.x += xv.y * wv.x; a1.y += xv.y * wv.y; a1.z += xv.y * wv.z; a1.w += xv.y * wv.w;
            a2.x += xv.z * wv.x; a2.y += xv.z * wv.y; a2.z += xv.z * wv.z; a2.w += xv.z * wv.w;
            a3.x += xv.w * wv.x; a3.y += xv.w * wv.y; a3.z += xv.w * wv.z; a3.w += xv.w * wv.w;
        }
        float* rb = red1 + fq * 512 + o4 * 4;
        *(float4*)&rb[0]   = a0;
        *(float4*)&rb[128] = a1;
        *(float4*)&rb[256] = a2;
        *(float4*)&rb[384] = a3;
    } else if (t < 384) {
        // ----- adjacency row i = blk, warp-cooperative (coalesced) -----
        const int t2 = t - 256;            // 0..127
        const int aw = t2 >> 5;            // warp 0..3
        const int lane = t & 31;
        float* ei     = sm + 4608;  // [128]
        float* sdot   = sm + 4736;  // [128]
        float* sinv   = sm + 4864;  // [128]
        float* simrow = sm + 4992;  // [128]
        ei[t2] = emb[blk * FF + t2];
        asm volatile("bar.sync 4, 128;" ::: "memory");

        const float4 eiv = ((const float4*)ei)[lane];
        const float4* emb4 = (const float4*)emb;
        for (int it = 0; it < 32; ++it) {
            const int j = aw * 32 + it;
            const float4 ev = emb4[j * 32 + lane];   // coalesced LDG.128
            float d  = ev.x * eiv.x + ev.y * eiv.y + ev.z * eiv.z + ev.w * eiv.w;
            float nr = ev.x * ev.x + ev.y * ev.y + ev.z * ev.z + ev.w * ev.w;
            #pragma unroll
            for (int m = 16; m >= 1; m >>= 1) {
                d  += __shfl_xor_sync(0xffffffffu, d, m);
                nr += __shfl_xor_sync(0xffffffffu, nr, m);
            }
            if (lane == it) { sdot[j] = d; sinv[j] = 1.0f / sqrtf(nr); }
        }
        asm volatile("bar.sync 4, 128;" ::: "memory");
        simrow[t2] = sdot[t2] * sinv[t2] * sinv[blk];
        asm volatile("bar.sync 4, 128;" ::: "memory");

        const int k = kptr ? *kptr : 30;
        const float mine = simrow[t2];
        int rank = 0;
        #pragma unroll 16
        for (int j = 0; j < NN; ++j) {
            const float v = simrow[j];               // broadcast LDS
            rank += (v > mine || (v == mine && j < t2)) ? 1 : 0;
        }
        adj_out[blk * NN + t2] = (rank < k) ? 1.0f : 0.0f;
    }
    __syncthreads();

    // finalize h0s4[f*4+r] (t<128)
    if (t < 128) {
        const int r = t >> 5, o4 = t & 31;
        const float* red1 = sm + 512;
        float4 s = {0,0,0,0};
        #pragma unroll
        for (int fq = 0; fq < 8; ++fq) {
            const float4 v = *(const float4*)&red1[fq * 512 + r * 128 + o4 * 4];
            s.x += v.x; s.y += v.y; s.z += v.z; s.w += v.w;
        }
        const float4 bv = ((const float4*)fpb)[o4];
        s.x += bv.x; s.y += bv.y; s.z += bv.z; s.w += bv.w;
        h0s4[(o4 * 4 + 0) * 4 + r] = s.x;
        h0s4[(o4 * 4 + 1) * 4 + r] = s.y;
        h0s4[(o4 * 4 + 2) * 4 + r] = s.z;
        h0s4[(o4 * 4 + 3) * 4 + r] = s.w;
    }
    __syncthreads();

    // ============ Phase 2: p[c][r] = relu(gatW[c] . h0[:,r]) ===============
    // Warp = 32 c-rows as 4 c-subgroups (csub) x 8 f-lanes (fl). Per (it,j)
    // instruction the warp reads 4 contiguous 128B chunks -> 4 wavefronts.
    // h0 lives in registers (16 float4/lane); reduce = 3 shfl_xor rounds.
    {
        const int w = t >> 5, lane = t & 31;
        const int fl = lane & 7, csub = lane >> 3;

        float4 hreg[4][4];   // [j][jj] = h0[f=4*(fl+8j)+jj][r=0..3]
        #pragma unroll
        for (int j = 0; j < 4; ++j)
            #pragma unroll
            for (int jj = 0; jj < 4; ++jj)
                hreg[j][jj] = *(const float4*)&h0s4[(4 * (fl + 8 * j) + jj) * 4];

        const float4* gw4 = (const float4*)gatW;
        #pragma unroll
        for (int it = 0; it < 8; ++it) {
            const int c = w * 32 + it * 4 + csub;
            float4 a = {0,0,0,0};
            #pragma unroll
            for (int j = 0; j < 4; ++j) {
                const float4 wv = gw4[c * 32 + fl + 8 * j];  // coalesced
                a.x += wv.x*hreg[j][0].x + wv.y*hreg[j][1].x + wv.z*hreg[j][2].x + wv.w*hreg[j][3].x;
                a.y += wv.x*hreg[j][0].y + wv.y*hreg[j][1].y + wv.z*hreg[j][2].y + wv.w*hreg[j][3].y;
                a.z += wv.x*hreg[j][0].z + wv.y*hreg[j][1].z + wv.z*hreg[j][2].z + wv.w*hreg[j][3].z;
                a.w += wv.x*hreg[j][0].w + wv.y*hreg[j][1].w + wv.z*hreg[j][2].w + wv.w*hreg[j][3].w;
            }
            #pragma unroll
            for (int m = 4; m >= 1; m >>= 1) {     // reduce over 8 f-lanes
                a.x += __shfl_xor_sync(0xffffffffu, a.x, m);
                a.y += __shfl_xor_sync(0xffffffffu, a.y, m);
                a.z += __shfl_xor_sync(0xffffffffu, a.z, m);
                a.w += __shfl_xor_sync(0xffffffffu, a.w, m);
            }
            if (fl == 0) {
                a.x = fmaxf(a.x, 0.f); a.y = fmaxf(a.y, 0.f);
                a.z = fmaxf(a.z, 0.f); a.w = fmaxf(a.w, 0.f);
                *(float4*)&ps4[c * 4] = a;
            }
        }
    }
    __syncthreads();

    // ============ Phase 3: imp = p @ opW + opb; blend ======================
    // 16 c-quarters x 32 n4; opW float4 along n (coalesced), p bcast LDS.
    {
        const int cq = t >> 5, n4 = t & 31;
        const float4* ow4 = (const float4*)opW;  // [c][n4]
        float4 acc0 = {0,0,0,0}, acc1 = {0,0,0,0},
               acc2 = {0,0,0,0}, acc3 = {0,0,0,0};
        const int c0 = cq * 32;
        #pragma unroll 8
        for (int c = c0; c < c0 + 32; ++c) {
            const float4 wv = ow4[c * 32 + n4];             // coalesced LDG.128
            const float4 pv = *(const float4*)&ps4[c * 4];  // bcast LDS.128
            acc0.x += pv.x * wv.x; acc0.y += pv.x * wv.y; acc0.z += pv.x * wv.z; acc0.w += pv.x * wv.w;
            acc1.x += pv.y * wv.x; acc1.y += pv.y * wv.y; acc1.z += pv.y * wv.z; acc1.w += pv.y * wv.w;
            acc2.x += pv.z * wv.x; acc2.y += pv.z * wv.y; acc2.z += pv.z * wv.z; acc2.w += pv.z * wv.w;
            acc3.x += pv.w * wv.x; acc3.y += pv.w * wv.y; acc3.z += pv.w * wv.z; acc3.w += pv.w * wv.w;
        }
        float* red3 = sm;  // [16 cq][4 r][32 n4][4]
        float* rb = red3 + (cq * 4) * 128 + n4 * 4;
        *(float4*)&rb[0]   = acc0;
        *(float4*)&rb[128] = acc1;
        *(float4*)&rb[256] = acc2;
        *(float4*)&rb[384] = acc3;
    }
    __syncthreads();

    if (t < 128) {
        const int r = t >> 5, n4 = t & 31;
        const float* red3 = sm;
        float4 s = {0,0,0,0};
        #pragma unroll
        for (int cq = 0; cq < 16; ++cq) {
            const float4 v = *(const float4*)&red3[cq * 512 + r * 128 + n4 * 4];
            s.x += v.x; s.y += v.y; s.z += v.z; s.w += v.w;
        }
        const float4 bv = ((const float4*)opb)[n4];
        s.x += bv.x; s.y += bv.y; s.z += bv.z; s.w += bv.w;

        const int i4 = ((b0 + r) * NN) / 4 + n4;
        const float4 xv = ((const float4*)x)[i4];
        const float4 mv = ((const float4*)mask)[i4];
        float4 o;
        o.x = xv.x * (1.0f - mv.x) + s.x * mv.x;
        o.y = xv.y * (1.0f - mv.y) + s.y * mv.y;
        o.z = xv.z * (1.0f - mv.z) + s.z * mv.z;
        o.w = xv.w * (1.0f - mv.w) + s.w * mv.w;
        ((float4*)out)[i4] = o;
    }
}

// ---------------------------------------------------------------------------
extern "C" void kernel_launch(void* const* d_in, const int* in_sizes, int n_in,
                              void* d_out, int out_size) {
    (void)in_sizes; (void)out_size;
    const float* x    = (const float*)d_in[0];
    const float* mask = (const float*)d_in[1];
    const float* emb  = (const float*)d_in[2];
    const float* gatW = (const float*)d_in[3];
    const float* fpW  = (const float*)d_in[5];
    const float* fpb  = (const float*)d_in[6];
    const float* opW  = (const float*)d_in[7];
    const float* opb  = (const float*)d_in[8];
    const int*   kptr = (n_in >= 10) ? (const int*)d_in[9] : nullptr;

    float* out = (float*)d_out;
    float* adj = out + BW * NN;

    fused_kernel<<<GRID, TPB>>>(x, mask, emb, gatW, fpW, fpb, opW, opb,
                                kptr, out, adj);
}